// round 1
// baseline (speedup 1.0000x reference)
#include <cuda_runtime.h>
#include <cuda_bf16.h>
#include <math.h>

// Problem constants
#define BB   32
#define LL   4096
#define HH   256
#define NN   512
#define CSROWS 137              // prefix rows 0..136
#define GM   (BB * CSROWS)      // 4384 GEMM rows
#define GN   1024               // [Ya | Yb | Ua | Ub]
#define BN_TOT (BB * NN)        // 16384 nodes

// ---------------- scratch (static device globals; no runtime alloc) ----------
__device__ float g_CS[BB * CSROWS * HH];        // prefix sums
__device__ float g_Wcat[HH * GN];               // [Wa | Wb | Wa@Wg1 | Wb@Wg1]
__device__ float g_Y[GM * GN];                  // CS @ Wcat
__device__ float g_node[BN_TOT * HH];
__device__ float g_Z[BN_TOT * HH];              // node @ Wg1
__device__ float g_nodeout[BN_TOT * HH];
__device__ float g_a2[BN_TOT];                  // leaky(node) . W_attn[H:2H]
__device__ float g_T[3 * HH];                   // W_trip[2H+s] + b_trip
__device__ float g_TZ[3 * HH];                  // T[s] @ Wg1
__device__ float g_Eg2[2 * HH];                 // edge_emb @ Wg2
__device__ float g_ae[2];                       // leaky(edge_emb) . W_attn[2H:]
__device__ int   g_order[2 * BB * NN];
__device__ int   g_start[2 * BB * 1025];
__device__ int   g_bflag[BB];

// ---------------- small prep: T, TZ, Eg2, ae, bflag zero ---------------------
__global__ void k_prep_small(const float* __restrict__ W_trip,
                             const float* __restrict__ b_trip,
                             const float* __restrict__ edge_emb,
                             const float* __restrict__ W_attn,
                             const float* __restrict__ W_gat) {
    __shared__ float Tsh[3][HH];
    __shared__ float red[HH];
    int h = threadIdx.x;  // 256 threads

    #pragma unroll
    for (int s = 0; s < 3; s++) {
        float v = W_trip[(2 * HH + s) * HH + h] + b_trip[h];
        Tsh[s][h] = v;
        g_T[s * HH + h] = v;
    }
    // Eg2[t][h] = sum_k edge_emb[t,k] * W_gat[H+k, h]
    #pragma unroll
    for (int t = 0; t < 2; t++) {
        float acc = 0.f;
        for (int k = 0; k < HH; k++)
            acc += edge_emb[t * HH + k] * W_gat[(HH + k) * HH + h];
        g_Eg2[t * HH + h] = acc;
    }
    __syncthreads();
    // TZ[s][h] = sum_k T[s][k] * W_gat[k, h]
    #pragma unroll
    for (int s = 0; s < 3; s++) {
        float acc = 0.f;
        for (int k = 0; k < HH; k++)
            acc += Tsh[s][k] * W_gat[k * HH + h];
        g_TZ[s * HH + h] = acc;
    }
    // ae[t] = sum_h leaky(edge_emb[t,h]) * W_attn[2H+h]
    for (int t = 0; t < 2; t++) {
        float e = edge_emb[t * HH + h];
        e = (e >= 0.f) ? e : 0.2f * e;
        red[h] = e * W_attn[2 * HH + h];
        __syncthreads();
        for (int off = 128; off; off >>= 1) {
            if (h < off) red[h] += red[h + off];
            __syncthreads();
        }
        if (h == 0) g_ae[t] = red[0];
        __syncthreads();
    }
    if (h < BB) g_bflag[h] = 0;
}

// ---------------- build Wcat ------------------------------------------------
__global__ void k_prep_wcat(const float* __restrict__ W_trip,
                            const float* __restrict__ W_gat) {
    int k = blockIdx.x;    // 0..255
    int j = threadIdx.x;   // 0..1023
    float out;
    if (j < HH) {
        out = W_trip[k * HH + j];                     // Wa
    } else if (j < 2 * HH) {
        out = W_trip[(HH + k) * HH + (j - HH)];       // Wb
    } else {
        int jj = j & (HH - 1);
        const float* wrow = (j < 3 * HH) ? &W_trip[k * HH] : &W_trip[(HH + k) * HH];
        float acc = 0.f;
        for (int m = 0; m < HH; m++)
            acc += wrow[m] * W_gat[m * HH + jj];
        out = acc;                                     // Wa@Wg1 / Wb@Wg1
    }
    g_Wcat[k * GN + j] = out;
}

// ---------------- prefix sums over first 136 rows -----------------------------
__global__ void k_prefix(const float* __restrict__ emb) {
    int b = blockIdx.x;      // 32 blocks
    int h = threadIdx.x;     // 256 threads
    const float* e = emb + (size_t)b * LL * HH + h;
    float* cs = g_CS + (size_t)b * CSROWS * HH + h;
    float acc = 0.f;
    cs[0] = 0.f;
    #pragma unroll 8
    for (int t = 0; t < CSROWS - 1; t++) {
        acc += e[(size_t)t * HH];
        cs[(size_t)(t + 1) * HH] = acc;
    }
}

// ---------------- SGEMM: Y[4384,1024] = CS[4384,256] @ Wcat[256,1024] --------
__global__ __launch_bounds__(256) void k_gemm() {
    __shared__ float As[16][64];   // transposed A tile: As[k][m]
    __shared__ float Bs[16][64];
    int bm = blockIdx.y, bn = blockIdx.x;
    int tid = threadIdx.x;
    int tx = tid & 15, ty = tid >> 4;
    int m_base = bm * 64, n_base = bn * 64;

    int arow = tid >> 2;          // 0..63
    int acol = (tid & 3) * 4;     // 0,4,8,12
    int brow = tid >> 4;          // 0..15
    int bcol = (tid & 15) * 4;    // 0..60

    float acc[4][4] = {};
    for (int k0 = 0; k0 < HH; k0 += 16) {
        int m = m_base + arow;
        float4 av = make_float4(0.f, 0.f, 0.f, 0.f);
        if (m < GM)
            av = *reinterpret_cast<const float4*>(&g_CS[(size_t)m * HH + k0 + acol]);
        As[acol + 0][arow] = av.x;
        As[acol + 1][arow] = av.y;
        As[acol + 2][arow] = av.z;
        As[acol + 3][arow] = av.w;
        float4 bv = *reinterpret_cast<const float4*>(
            &g_Wcat[(size_t)(k0 + brow) * GN + n_base + bcol]);
        *reinterpret_cast<float4*>(&Bs[brow][bcol]) = bv;
        __syncthreads();
        #pragma unroll
        for (int k = 0; k < 16; k++) {
            float4 a = *reinterpret_cast<const float4*>(&As[k][ty * 4]);
            float4 b = *reinterpret_cast<const float4*>(&Bs[k][tx * 4]);
            float ar[4] = {a.x, a.y, a.z, a.w};
            float br[4] = {b.x, b.y, b.z, b.w};
            #pragma unroll
            for (int i = 0; i < 4; i++)
                #pragma unroll
                for (int j = 0; j < 4; j++)
                    acc[i][j] += ar[i] * br[j];
        }
        __syncthreads();
    }
    #pragma unroll
    for (int i = 0; i < 4; i++) {
        int m = m_base + ty * 4 + i;
        if (m < GM) {
            #pragma unroll
            for (int j = 0; j < 4; j++)
                g_Y[(size_t)m * GN + n_base + tx * 4 + j] = acc[i][j];
        }
    }
}

// ---------------- node / Z / a_src materialization ---------------------------
__global__ __launch_bounds__(256) void k_node(const int* __restrict__ asp_st,
                                              const int* __restrict__ asp_len,
                                              const int* __restrict__ opi_st,
                                              const int* __restrict__ opi_len,
                                              const int* __restrict__ sent,
                                              const float* __restrict__ W_attn) {
    __shared__ float red[HH];
    int bn = blockIdx.x;            // 0..16383
    int b = bn >> 9;
    int h = threadIdx.x;            // 256
    int as = asp_st[bn], al = asp_len[bn];
    int os = opi_st[bn], ol = opi_len[bn];
    int s = sent[bn];
    float inva = 1.f / (float)(al + 1);
    float invo = 1.f / (float)(ol + 1);
    const float* Yb = g_Y + (size_t)b * CSROWS * GN;
    const float* rA0 = Yb + (size_t)as * GN;
    const float* rA1 = Yb + (size_t)(as + al + 1) * GN;
    const float* rO0 = Yb + (size_t)os * GN;
    const float* rO1 = Yb + (size_t)(os + ol + 1) * GN;

    float nv = (rA1[h] - rA0[h]) * inva + (rO1[HH + h] - rO0[HH + h]) * invo
             + g_T[s * HH + h];
    float zv = (rA1[2 * HH + h] - rA0[2 * HH + h]) * inva
             + (rO1[3 * HH + h] - rO0[3 * HH + h]) * invo
             + g_TZ[s * HH + h];
    g_node[(size_t)bn * HH + h] = nv;
    g_Z[(size_t)bn * HH + h] = zv;

    float ln = (nv >= 0.f) ? nv : 0.2f * nv;
    red[h] = ln * W_attn[HH + h];
    __syncthreads();
    for (int off = 128; off; off >>= 1) {
        if (h < off) red[h] += red[h + off];
        __syncthreads();
    }
    if (h == 0) g_a2[bn] = red[0];
}

// ---------------- bucket build (counting sort per batch, per type) -----------
__global__ __launch_bounds__(1024) void k_bucket(const int* __restrict__ asp_st,
                                                 const int* __restrict__ asp_len,
                                                 const int* __restrict__ opi_st,
                                                 const int* __restrict__ opi_len) {
    __shared__ int cnt[1024];
    __shared__ int offs[1024];
    __shared__ int keys[NN];
    int bx = blockIdx.x;                // 0..63
    int type = bx >> 5;
    int b = bx & 31;
    int t = threadIdx.x;                // 0..1023

    cnt[t] = 0;
    __syncthreads();
    if (t < NN) {
        int bn = b * NN + t;
        int key = (type == 0) ? asp_st[bn] * 8 + asp_len[bn]
                              : opi_st[bn] * 8 + opi_len[bn];
        keys[t] = key;
        atomicAdd(&cnt[key], 1);
    }
    __syncthreads();
    int myc = cnt[t];
    // Hillis-Steele inclusive scan (in place)
    for (int off = 1; off < 1024; off <<= 1) {
        int add = (t >= off) ? cnt[t - off] : 0;
        __syncthreads();
        cnt[t] += add;
        __syncthreads();
    }
    int excl = cnt[t] - myc;
    int* st = g_start + (type * BB + b) * 1025;
    st[t] = excl;
    if (t == 1023) st[1024] = cnt[1023];
    offs[t] = excl;
    __syncthreads();
    if (t < NN) {
        int pos = atomicAdd(&offs[keys[t]], 1);
        g_order[(type * BB + b) * NN + pos] = t;
    }
}

// ---------------- edges + softmax + GAT update (one warp per target) ---------
__global__ __launch_bounds__(256) void k_edges(const int* __restrict__ asp_st,
                                               const int* __restrict__ asp_len,
                                               const int* __restrict__ opi_st,
                                               const int* __restrict__ opi_len,
                                               const float* __restrict__ b_gat) {
    int wg = (blockIdx.x * blockDim.x + threadIdx.x) >> 5;
    if (wg >= BN_TOT) return;
    int lane = threadIdx.x & 31;
    int b = wg >> 9;
    int tgt = wg & 511;
    int bn = wg;

    float nt[8];
    #pragma unroll
    for (int i = 0; i < 8; i++)
        nt[i] = g_node[(size_t)bn * HH + lane + i * 32];

    int key0 = asp_st[bn] * 8 + asp_len[bn];
    int key1 = opi_st[bn] * 8 + opi_len[bn];

    float m = -3.0e38f;
    int cnt = 0;
    // pass 1: find edges, compute max score (a_tgt/b_attn cancel)
    for (int ty = 0; ty < 2; ty++) {
        int key = ty ? key1 : key0;
        const int* st = g_start + (ty * BB + b) * 1025;
        const int* ord = g_order + (ty * BB + b) * NN;
        int s0 = st[key], s1 = st[key + 1];
        for (int idx = s0; idx < s1; idx++) {
            int src = ord[idx];
            if (src == tgt) continue;
            int sb = b * NN + src;
            float d = 0.f;
            #pragma unroll
            for (int i = 0; i < 8; i++)
                d += nt[i] * g_node[(size_t)sb * HH + lane + i * 32];
            #pragma unroll
            for (int off = 16; off; off >>= 1)
                d += __shfl_xor_sync(0xffffffffu, d, off);
            if (d > 0.f) {
                cnt++;
                float sc = g_a2[sb] + g_ae[ty];
                m = fmaxf(m, sc);
            }
        }
    }
    if (cnt == 0) {
        #pragma unroll
        for (int i = 0; i < 8; i++)
            g_nodeout[(size_t)bn * HH + lane + i * 32] = nt[i];
        return;
    }
    if (lane == 0) g_bflag[b] = 1;

    float S = 0.f, e0 = 0.f, e1 = 0.f;
    float acc[8] = {};
    // pass 2: softmax-weighted aggregation of Z (= node@Wg1)
    for (int ty = 0; ty < 2; ty++) {
        int key = ty ? key1 : key0;
        const int* st = g_start + (ty * BB + b) * 1025;
        const int* ord = g_order + (ty * BB + b) * NN;
        int s0 = st[key], s1 = st[key + 1];
        for (int idx = s0; idx < s1; idx++) {
            int src = ord[idx];
            if (src == tgt) continue;
            int sb = b * NN + src;
            float d = 0.f;
            #pragma unroll
            for (int i = 0; i < 8; i++)
                d += nt[i] * g_node[(size_t)sb * HH + lane + i * 32];
            #pragma unroll
            for (int off = 16; off; off >>= 1)
                d += __shfl_xor_sync(0xffffffffu, d, off);
            if (d > 0.f) {
                float p = expf(g_a2[sb] + g_ae[ty] - m);
                S += p;
                if (ty == 0) e0 += p; else e1 += p;
                #pragma unroll
                for (int i = 0; i < 8; i++)
                    acc[i] += p * g_Z[(size_t)sb * HH + lane + i * 32];
            }
        }
    }
    float invS = 1.f / S;
    #pragma unroll
    for (int i = 0; i < 8; i++) {
        int h = lane + i * 32;
        float u = acc[i] * invS + e0 * invS * g_Eg2[h]
                + e1 * invS * g_Eg2[HH + h] + b_gat[h];
        g_nodeout[(size_t)bn * HH + h] = fmaxf(u, 0.f);
    }
}

// ---------------- scatter-add into output ------------------------------------
__global__ __launch_bounds__(256) void k_scatter(const int* __restrict__ asp_st,
                                                 const int* __restrict__ opi_st,
                                                 float* __restrict__ out) {
    int idx = blockIdx.x * blockDim.x + threadIdx.x;
    if (idx >= BN_TOT * HH) return;
    int bn = idx >> 8;
    int h = idx & 255;
    int b = bn >> 9;
    if (!g_bflag[b]) return;
    int c = (asp_st[bn] + opi_st[bn]) >> 1;
    atomicAdd(&out[((size_t)b * LL + c) * HH + h], g_nodeout[(size_t)bn * HH + h]);
}

// ---------------- launch ------------------------------------------------------
extern "C" void kernel_launch(void* const* d_in, const int* in_sizes, int n_in,
                              void* d_out, int out_size) {
    const float* emb      = (const float*)d_in[0];
    const float* W_trip   = (const float*)d_in[1];
    const float* b_trip   = (const float*)d_in[2];
    const float* edge_emb = (const float*)d_in[3];
    const float* W_attn   = (const float*)d_in[4];
    // d_in[5] = b_attn (cancels in softmax)
    const float* W_gat    = (const float*)d_in[6];
    const float* b_gat    = (const float*)d_in[7];
    const int* asp_st  = (const int*)d_in[8];
    const int* asp_len = (const int*)d_in[9];
    const int* opi_st  = (const int*)d_in[10];
    const int* opi_len = (const int*)d_in[11];
    const int* sent    = (const int*)d_in[12];
    float* out = (float*)d_out;

    // copy embeddings -> out (base of "enhanced")
    cudaMemcpyAsync(out, emb, (size_t)BB * LL * HH * sizeof(float),
                    cudaMemcpyDeviceToDevice, 0);

    k_prep_small<<<1, 256>>>(W_trip, b_trip, edge_emb, W_attn, W_gat);
    k_prep_wcat<<<HH, 1024>>>(W_trip, W_gat);
    k_prefix<<<BB, 256>>>(emb);
    {
        dim3 grid(GN / 64, (GM + 63) / 64);
        k_gemm<<<grid, 256>>>();
    }
    k_node<<<BN_TOT, 256>>>(asp_st, asp_len, opi_st, opi_len, sent, W_attn);
    k_bucket<<<2 * BB, 1024>>>(asp_st, asp_len, opi_st, opi_len);
    k_edges<<<(BN_TOT * 32 + 255) / 256, 256>>>(asp_st, asp_len, opi_st, opi_len, b_gat);
    k_scatter<<<(BN_TOT * HH + 255) / 256, 256>>>(asp_st, opi_st, out);
}

// round 4
// speedup vs baseline: 1.1072x; 1.1072x over previous
#include <cuda_runtime.h>
#include <cuda_bf16.h>
#include <math.h>

// Problem constants
#define BB   32
#define LL   4096
#define HH   256
#define NN   512
#define CSROWS 137              // prefix rows 0..136
#define GM   (BB * CSROWS)      // 4384 GEMM rows
#define GN   1024               // [Ya | Yb | Ua | Ub]
#define BN_TOT (BB * NN)        // 16384 nodes
#define CMAX 128                // centers always < 128

// ---------------- scratch (static device globals; no runtime alloc) ----------
__device__ float g_CS[BB * CSROWS * HH];        // prefix sums
__device__ float g_Wcat[HH * GN];               // [Wa | Wb | Wa@Wg1 | Wb@Wg1]
__device__ float g_Y[GM * GN];                  // CS @ Wcat
__device__ float g_node[BN_TOT * HH];
__device__ float g_Z[BN_TOT * HH];              // node @ Wg1
__device__ float g_nodeout[BN_TOT * HH];
__device__ float g_a2[BN_TOT];                  // leaky(node) . W_attn[H:2H]
__device__ float g_T[3 * HH];                   // W_trip[2H+s] + b_trip
__device__ float g_TZ[3 * HH];                  // T[s] @ Wg1
__device__ float g_Eg2[2 * HH];                 // edge_emb @ Wg2
__device__ float g_ae[2];                       // leaky(edge_emb) . W_attn[2H:]
__device__ float g_add[BB * CMAX * HH];         // dense scatter staging (4 MB)
__device__ int   g_order[2 * BB * NN];
__device__ int   g_start[2 * BB * 1025];
__device__ int   g_bflag[BB];

// ---------------- zero staging buffer + flags --------------------------------
// 1024 blocks * 256 threads * 4 floats = exactly BB*CMAX*HH floats.
__global__ void k_zero() {
    int idx = blockIdx.x * blockDim.x + threadIdx.x;
    *reinterpret_cast<float4*>(&g_add[(size_t)idx * 4]) =
        make_float4(0.f, 0.f, 0.f, 0.f);
    if (blockIdx.x == 0 && threadIdx.x < BB) g_bflag[threadIdx.x] = 0;
}

// ---------------- small prep: T, TZ, Eg2, ae ---------------------------------
__global__ void k_prep_small(const float* __restrict__ W_trip,
                             const float* __restrict__ b_trip,
                             const float* __restrict__ edge_emb,
                             const float* __restrict__ W_attn,
                             const float* __restrict__ W_gat) {
    __shared__ float Tsh[3][HH];
    __shared__ float red[HH];
    int h = threadIdx.x;  // 256 threads

    #pragma unroll
    for (int s = 0; s < 3; s++) {
        float v = W_trip[(2 * HH + s) * HH + h] + b_trip[h];
        Tsh[s][h] = v;
        g_T[s * HH + h] = v;
    }
    #pragma unroll
    for (int t = 0; t < 2; t++) {
        float acc = 0.f;
        for (int k = 0; k < HH; k++)
            acc += edge_emb[t * HH + k] * W_gat[(HH + k) * HH + h];
        g_Eg2[t * HH + h] = acc;
    }
    __syncthreads();
    #pragma unroll
    for (int s = 0; s < 3; s++) {
        float acc = 0.f;
        for (int k = 0; k < HH; k++)
            acc += Tsh[s][k] * W_gat[k * HH + h];
        g_TZ[s * HH + h] = acc;
    }
    for (int t = 0; t < 2; t++) {
        float e = edge_emb[t * HH + h];
        e = (e >= 0.f) ? e : 0.2f * e;
        red[h] = e * W_attn[2 * HH + h];
        __syncthreads();
        for (int off = 128; off; off >>= 1) {
            if (h < off) red[h] += red[h + off];
            __syncthreads();
        }
        if (h == 0) g_ae[t] = red[0];
        __syncthreads();
    }
}

// ---------------- build Wcat -------------------------------------------------
__global__ void k_prep_wcat(const float* __restrict__ W_trip,
                            const float* __restrict__ W_gat) {
    int k = blockIdx.x;    // 0..255
    int j = threadIdx.x;   // 0..1023
    float out;
    if (j < HH) {
        out = W_trip[k * HH + j];                     // Wa
    } else if (j < 2 * HH) {
        out = W_trip[(HH + k) * HH + (j - HH)];       // Wb
    } else {
        int jj = j & (HH - 1);
        const float* wrow = (j < 3 * HH) ? &W_trip[k * HH] : &W_trip[(HH + k) * HH];
        float acc = 0.f;
        for (int m = 0; m < HH; m++)
            acc += wrow[m] * W_gat[m * HH + jj];
        out = acc;                                     // Wa@Wg1 / Wb@Wg1
    }
    g_Wcat[k * GN + j] = out;
}

// ---------------- prefix sums over first 136 rows ----------------------------
__global__ void k_prefix(const float* __restrict__ emb) {
    int b = blockIdx.x;      // 32 blocks
    int h = threadIdx.x;     // 256 threads
    const float* e = emb + (size_t)b * LL * HH + h;
    float* cs = g_CS + (size_t)b * CSROWS * HH + h;
    float acc = 0.f;
    cs[0] = 0.f;
    #pragma unroll 8
    for (int t = 0; t < CSROWS - 1; t++) {
        acc += e[(size_t)t * HH];
        cs[(size_t)(t + 1) * HH] = acc;
    }
}

// ---------------- SGEMM: Y[4384,1024] = CS[4384,256] @ Wcat[256,1024] --------
// 128x128 block tile, BK=8, 8x8 per thread in 4+4 split layout.
__global__ __launch_bounds__(256) void k_gemm2() {
    __shared__ float As[8][128];
    __shared__ float Bs[8][128];
    int tid = threadIdx.x;
    int tx = tid & 15;            // 0..15 (col group)
    int ty = tid >> 4;            // 0..15 (row group)
    int m_base = blockIdx.y * 128;
    int n_base = blockIdx.x * 128;

    int a_row = tid >> 1;         // 0..127
    int a_col = (tid & 1) * 4;    // 0 or 4
    int b_row = tid >> 5;         // 0..7
    int b_col = (tid & 31) * 4;   // 0..124

    bool a_ok = (m_base + a_row) < GM;
    const float* a_src = &g_CS[(size_t)(m_base + a_row) * HH + a_col];
    const float* b_src = &g_Wcat[(size_t)b_row * GN + n_base + b_col];

    float acc[8][8];
    #pragma unroll
    for (int i = 0; i < 8; i++)
        #pragma unroll
        for (int j = 0; j < 8; j++) acc[i][j] = 0.f;

    for (int k0 = 0; k0 < HH; k0 += 8) {
        float4 av = make_float4(0.f, 0.f, 0.f, 0.f);
        if (a_ok) av = *reinterpret_cast<const float4*>(a_src + k0);
        float4 bv = *reinterpret_cast<const float4*>(b_src + (size_t)k0 * GN);
        As[a_col + 0][a_row] = av.x;
        As[a_col + 1][a_row] = av.y;
        As[a_col + 2][a_row] = av.z;
        As[a_col + 3][a_row] = av.w;
        *reinterpret_cast<float4*>(&Bs[b_row][b_col]) = bv;
        __syncthreads();
        #pragma unroll
        for (int k = 0; k < 8; k++) {
            float4 a0 = *reinterpret_cast<const float4*>(&As[k][ty * 4]);
            float4 a1 = *reinterpret_cast<const float4*>(&As[k][ty * 4 + 64]);
            float4 b0 = *reinterpret_cast<const float4*>(&Bs[k][tx * 4]);
            float4 b1 = *reinterpret_cast<const float4*>(&Bs[k][tx * 4 + 64]);
            float ar[8] = {a0.x, a0.y, a0.z, a0.w, a1.x, a1.y, a1.z, a1.w};
            float br[8] = {b0.x, b0.y, b0.z, b0.w, b1.x, b1.y, b1.z, b1.w};
            #pragma unroll
            for (int i = 0; i < 8; i++)
                #pragma unroll
                for (int j = 0; j < 8; j++)
                    acc[i][j] += ar[i] * br[j];
        }
        __syncthreads();
    }

    #pragma unroll
    for (int g = 0; g < 2; g++) {
        #pragma unroll
        for (int i = 0; i < 4; i++) {
            int m = m_base + g * 64 + ty * 4 + i;
            if (m < GM) {
                float* dst = &g_Y[(size_t)m * GN + n_base];
                *reinterpret_cast<float4*>(dst + tx * 4) =
                    make_float4(acc[g * 4 + i][0], acc[g * 4 + i][1],
                                acc[g * 4 + i][2], acc[g * 4 + i][3]);
                *reinterpret_cast<float4*>(dst + tx * 4 + 64) =
                    make_float4(acc[g * 4 + i][4], acc[g * 4 + i][5],
                                acc[g * 4 + i][6], acc[g * 4 + i][7]);
            }
        }
    }
}

// ---------------- node / Z / a_src materialization ---------------------------
__global__ __launch_bounds__(256) void k_node(const int* __restrict__ asp_st,
                                              const int* __restrict__ asp_len,
                                              const int* __restrict__ opi_st,
                                              const int* __restrict__ opi_len,
                                              const int* __restrict__ sent,
                                              const float* __restrict__ W_attn) {
    __shared__ float red8[8];
    int bn = blockIdx.x;            // 0..16383
    int b = bn >> 9;
    int h = threadIdx.x;            // 256
    int as = asp_st[bn], al = asp_len[bn];
    int os = opi_st[bn], ol = opi_len[bn];
    int s = sent[bn];
    float inva = 1.f / (float)(al + 1);
    float invo = 1.f / (float)(ol + 1);
    const float* Yb = g_Y + (size_t)b * CSROWS * GN;
    const float* rA0 = Yb + (size_t)as * GN;
    const float* rA1 = Yb + (size_t)(as + al + 1) * GN;
    const float* rO0 = Yb + (size_t)os * GN;
    const float* rO1 = Yb + (size_t)(os + ol + 1) * GN;

    float nv = (rA1[h] - rA0[h]) * inva + (rO1[HH + h] - rO0[HH + h]) * invo
             + g_T[s * HH + h];
    float zv = (rA1[2 * HH + h] - rA0[2 * HH + h]) * inva
             + (rO1[3 * HH + h] - rO0[3 * HH + h]) * invo
             + g_TZ[s * HH + h];
    g_node[(size_t)bn * HH + h] = nv;
    g_Z[(size_t)bn * HH + h] = zv;

    float ln = (nv >= 0.f) ? nv : 0.2f * nv;
    float v = ln * W_attn[HH + h];
    #pragma unroll
    for (int off = 16; off; off >>= 1)
        v += __shfl_xor_sync(0xffffffffu, v, off);
    if ((h & 31) == 0) red8[h >> 5] = v;
    __syncthreads();
    if (h == 0) {
        float t = 0.f;
        #pragma unroll
        for (int w = 0; w < 8; w++) t += red8[w];
        g_a2[bn] = t;
    }
}

// ---------------- bucket build (counting sort per batch, per type) -----------
__global__ __launch_bounds__(1024) void k_bucket(const int* __restrict__ asp_st,
                                                 const int* __restrict__ asp_len,
                                                 const int* __restrict__ opi_st,
                                                 const int* __restrict__ opi_len) {
    __shared__ int cnt[1024];
    __shared__ int offs[1024];
    __shared__ int keys[NN];
    int bx = blockIdx.x;                // 0..63
    int type = bx >> 5;
    int b = bx & 31;
    int t = threadIdx.x;                // 0..1023

    cnt[t] = 0;
    __syncthreads();
    if (t < NN) {
        int bn = b * NN + t;
        int key = (type == 0) ? asp_st[bn] * 8 + asp_len[bn]
                              : opi_st[bn] * 8 + opi_len[bn];
        keys[t] = key;
        atomicAdd(&cnt[key], 1);
    }
    __syncthreads();
    int myc = cnt[t];
    for (int off = 1; off < 1024; off <<= 1) {
        int add = (t >= off) ? cnt[t - off] : 0;
        __syncthreads();
        cnt[t] += add;
        __syncthreads();
    }
    int excl = cnt[t] - myc;
    int* st = g_start + (type * BB + b) * 1025;
    st[t] = excl;
    if (t == 1023) st[1024] = cnt[1023];
    offs[t] = excl;
    __syncthreads();
    if (t < NN) {
        int pos = atomicAdd(&offs[keys[t]], 1);
        g_order[(type * BB + b) * NN + pos] = t;
    }
}

// ---------------- edges + online softmax + GAT (one warp per target) ---------
__global__ __launch_bounds__(256) void k_edges(const int* __restrict__ asp_st,
                                               const int* __restrict__ asp_len,
                                               const int* __restrict__ opi_st,
                                               const int* __restrict__ opi_len,
                                               const float* __restrict__ b_gat) {
    int wg = (blockIdx.x * blockDim.x + threadIdx.x) >> 5;
    if (wg >= BN_TOT) return;
    int lane = threadIdx.x & 31;
    int b = wg >> 9;
    int tgt = wg & 511;
    int bn = wg;

    float nt[8];
    #pragma unroll
    for (int i = 0; i < 8; i++)
        nt[i] = g_node[(size_t)bn * HH + lane + i * 32];

    int key0 = asp_st[bn] * 8 + asp_len[bn];
    int key1 = opi_st[bn] * 8 + opi_len[bn];

    float m = -3.0e38f;
    float S = 0.f, e0 = 0.f, e1 = 0.f;
    float acc[8] = {};

    // single pass: edge detection + online softmax aggregation of Z
    #pragma unroll
    for (int ty = 0; ty < 2; ty++) {
        int key = ty ? key1 : key0;
        const int* st = g_start + (ty * BB + b) * 1025;
        const int* ord = g_order + (ty * BB + b) * NN;
        int s0 = st[key], s1 = st[key + 1];
        float ae = g_ae[ty];
        for (int idx = s0; idx < s1; idx++) {
            int src = ord[idx];
            if (src == tgt) continue;
            int sb = b * NN + src;
            float d = 0.f;
            #pragma unroll
            for (int i = 0; i < 8; i++)
                d += nt[i] * g_node[(size_t)sb * HH + lane + i * 32];
            #pragma unroll
            for (int off = 16; off; off >>= 1)
                d += __shfl_xor_sync(0xffffffffu, d, off);
            if (d > 0.f) {
                float sc = g_a2[sb] + ae;
                float p;
                if (sc > m) {
                    float scale = expf(m - sc);   // 0 on first edge
                    S *= scale; e0 *= scale; e1 *= scale;
                    #pragma unroll
                    for (int i = 0; i < 8; i++) acc[i] *= scale;
                    m = sc;
                    p = 1.f;
                } else {
                    p = expf(sc - m);
                }
                S += p;
                if (ty == 0) e0 += p; else e1 += p;
                #pragma unroll
                for (int i = 0; i < 8; i++)
                    acc[i] += p * g_Z[(size_t)sb * HH + lane + i * 32];
            }
        }
    }

    if (S == 0.f) {  // no neighbors: keep node
        #pragma unroll
        for (int i = 0; i < 8; i++)
            g_nodeout[(size_t)bn * HH + lane + i * 32] = nt[i];
        return;
    }
    if (lane == 0) g_bflag[b] = 1;

    float invS = 1.f / S;
    #pragma unroll
    for (int i = 0; i < 8; i++) {
        int h = lane + i * 32;
        float u = acc[i] * invS + e0 * invS * g_Eg2[h]
                + e1 * invS * g_Eg2[HH + h] + b_gat[h];
        g_nodeout[(size_t)bn * HH + h] = fmaxf(u, 0.f);
    }
}

// ---------------- scatter-add into dense staging (L2-resident) ---------------
__global__ __launch_bounds__(256) void k_scatter(const int* __restrict__ asp_st,
                                                 const int* __restrict__ opi_st) {
    int idx = blockIdx.x * blockDim.x + threadIdx.x;
    int bn = idx >> 8;
    int h = idx & 255;
    int b = bn >> 9;
    int c = (asp_st[bn] + opi_st[bn]) >> 1;          // always < 128
    atomicAdd(&g_add[((b << 7) + c) * HH + h], g_nodeout[(size_t)bn * HH + h]);
}

// ---------------- fused output: out = emb (+ add on rows < 128) --------------
__global__ __launch_bounds__(256) void k_out(const float* __restrict__ emb,
                                             float* __restrict__ out) {
    int idx = blockIdx.x * blockDim.x + threadIdx.x;   // 8,388,608 float4s
    size_t base = (size_t)idx * 4;
    int b = (int)(base >> 20);                // / (LL*HH)
    int rem = (int)(base & (LL * HH - 1));
    int l = rem >> 8;
    float4 v = *reinterpret_cast<const float4*>(emb + base);
    if (l < CMAX && g_bflag[b]) {
        const float* a = &g_add[((b << 7) + l) * HH + (rem & 255)];
        v.x += a[0]; v.y += a[1]; v.z += a[2]; v.w += a[3];
    }
    *reinterpret_cast<float4*>(out + base) = v;
}

// ---------------- launch -----------------------------------------------------
extern "C" void kernel_launch(void* const* d_in, const int* in_sizes, int n_in,
                              void* d_out, int out_size) {
    const float* emb      = (const float*)d_in[0];
    const float* W_trip   = (const float*)d_in[1];
    const float* b_trip   = (const float*)d_in[2];
    const float* edge_emb = (const float*)d_in[3];
    const float* W_attn   = (const float*)d_in[4];
    // d_in[5] = b_attn (cancels in softmax)
    const float* W_gat    = (const float*)d_in[6];
    const float* b_gat    = (const float*)d_in[7];
    const int* asp_st  = (const int*)d_in[8];
    const int* asp_len = (const int*)d_in[9];
    const int* opi_st  = (const int*)d_in[10];
    const int* opi_len = (const int*)d_in[11];
    const int* sent    = (const int*)d_in[12];
    float* out = (float*)d_out;

    k_zero<<<1024, 256>>>();
    k_prep_small<<<1, 256>>>(W_trip, b_trip, edge_emb, W_attn, W_gat);
    k_prep_wcat<<<HH, 1024>>>(W_trip, W_gat);
    k_prefix<<<BB, 256>>>(emb);
    {
        dim3 grid(GN / 128, (GM + 127) / 128);
        k_gemm2<<<grid, 256>>>();
    }
    k_node<<<BN_TOT, 256>>>(asp_st, asp_len, opi_st, opi_len, sent, W_attn);
    k_bucket<<<2 * BB, 1024>>>(asp_st, asp_len, opi_st, opi_len);
    k_edges<<<(BN_TOT * 32 + 255) / 256, 256>>>(asp_st, asp_len, opi_st, opi_len, b_gat);
    k_scatter<<<(BN_TOT * HH + 255) / 256, 256>>>(asp_st, opi_st);
    k_out<<<32768, 256>>>(emb, out);
}

// round 7
// speedup vs baseline: 1.5054x; 1.3597x over previous
#include <cuda_runtime.h>
#include <cuda_bf16.h>
#include <math.h>

// Problem constants
#define BB   32
#define LL   4096
#define HH   256
#define NN   512
#define CSROWS 137              // prefix rows 0..136
#define GM   (BB * CSROWS)      // 4384 GEMM rows
#define GN   1024               // [Ya | Yb | Ua | Ub]
#define BN_TOT (BB * NN)        // 16384 nodes
#define CMAX 128                // centers always < 128
#define NCHUNK 8                // prefix chunks (136 = 8*17)
#define CHROWS 17

// ---------------- scratch (static device globals; no runtime alloc) ----------
__device__ float g_CS[BB * CSROWS * HH];        // prefix sums
__device__ float g_ptot[BB * NCHUNK * HH];      // per-chunk totals
__device__ float g_Wcat[HH * GN];               // [Wa | Wb | Wa@Wg1 | Wb@Wg1]
__device__ float g_Y[GM * GN];                  // CS @ Wcat
__device__ float g_node[BN_TOT * HH];
__device__ float g_Z[BN_TOT * HH];              // node @ Wg1
__device__ float g_a2[BN_TOT];                  // leaky(node) . W_attn[H:2H]
__device__ float g_T[3 * HH];                   // W_trip[2H+s] + b_trip
__device__ float g_TZ[3 * HH];                  // T[s] @ Wg1
__device__ float g_Eg2[2 * HH];                 // edge_emb @ Wg2
__device__ float g_ae[2];                       // leaky(edge_emb) . W_attn[2H:]
__device__ float g_add[BB * CMAX * HH];         // dense scatter staging (4 MB)
__device__ int   g_order[2 * BB * NN];
__device__ int   g_start[2 * BB * 1025];
__device__ int   g_bflag[BB];

// ---------------- fused setup: zero | bucket | prefixA | small preps | wcat --
// blockDim = 1024.  Block ranges:
//   [0,256)    zero g_add (+bflag in block 0)
//   [256,320)  bucket counting sort (64 blocks)
//   [320,576)  prefix phase A (32 b x 8 chunks)
//   576        T + ae
//   [577,579)  Eg2 (t = 0,1)
//   [579,582)  TZ  (s = 0..2)
//   [582,838)  Wcat (k = 0..255)
#define SB_ZERO   0
#define SB_BUCKET 256
#define SB_PREFIX 320
#define SB_TAE    576
#define SB_EG2    577
#define SB_TZ     579
#define SB_WCAT   582
#define SB_TOTAL  838

__global__ __launch_bounds__(1024) void k_setup(
    const float* __restrict__ emb,
    const float* __restrict__ W_trip,
    const float* __restrict__ b_trip,
    const float* __restrict__ edge_emb,
    const float* __restrict__ W_attn,
    const float* __restrict__ W_gat,
    const int* __restrict__ asp_st,
    const int* __restrict__ asp_len,
    const int* __restrict__ opi_st,
    const int* __restrict__ opi_len)
{
    int blk = blockIdx.x;
    int tid = threadIdx.x;

    if (blk < SB_BUCKET) {
        // ---- zero g_add: 256 blocks * 1024 threads * 1 float4 = 1M floats
        int idx = blk * 1024 + tid;
        *reinterpret_cast<float4*>(&g_add[(size_t)idx * 4]) =
            make_float4(0.f, 0.f, 0.f, 0.f);
        if (blk == 0 && tid < BB) g_bflag[tid] = 0;
        return;
    }

    if (blk < SB_PREFIX) {
        // ---- bucket counting sort: 64 blocks (type*32 + b)
        __shared__ int cnt[1024];
        __shared__ int offs[1024];
        __shared__ int keys[NN];
        int bx = blk - SB_BUCKET;
        int type = bx >> 5;
        int b = bx & 31;
        int t = tid;

        cnt[t] = 0;
        __syncthreads();
        if (t < NN) {
            int bn = b * NN + t;
            int key = (type == 0) ? asp_st[bn] * 8 + asp_len[bn]
                                  : opi_st[bn] * 8 + opi_len[bn];
            keys[t] = key;
            atomicAdd(&cnt[key], 1);
        }
        __syncthreads();
        int myc = cnt[t];
        for (int off = 1; off < 1024; off <<= 1) {
            int add = (t >= off) ? cnt[t - off] : 0;
            __syncthreads();
            cnt[t] += add;
            __syncthreads();
        }
        int excl = cnt[t] - myc;
        int* st = g_start + (type * BB + b) * 1025;
        st[t] = excl;
        if (t == 1023) st[1024] = cnt[1023];
        offs[t] = excl;
        __syncthreads();
        if (t < NN) {
            int pos = atomicAdd(&offs[keys[t]], 1);
            g_order[(type * BB + b) * NN + pos] = t;
        }
        return;
    }

    if (blk < SB_TAE) {
        // ---- prefix phase A: 256 blocks, (b, chunk c)
        if (tid >= HH) return;
        int bx = blk - SB_PREFIX;
        int b = bx >> 3;
        int c = bx & 7;
        int h = tid;
        const float* e = emb + (size_t)b * LL * HH + h;
        float* cs = g_CS + (size_t)b * CSROWS * HH + h;
        if (c == 0) cs[0] = 0.f;
        float acc = 0.f;
        int t0 = c * CHROWS;
        #pragma unroll
        for (int r = 0; r < CHROWS; r++) {
            acc += e[(size_t)(t0 + r) * HH];
            cs[(size_t)(t0 + r + 1) * HH] = acc;
        }
        g_ptot[((b << 3) + c) * HH + h] = acc;
        return;
    }

    if (blk == SB_TAE) {
        // ---- T + ae
        __shared__ float red[HH];
        if (tid < HH) {
            #pragma unroll
            for (int s = 0; s < 3; s++)
                g_T[s * HH + tid] = W_trip[(2 * HH + s) * HH + tid] + b_trip[tid];
        }
        for (int t = 0; t < 2; t++) {
            if (tid < HH) {
                float e = edge_emb[t * HH + tid];
                e = (e >= 0.f) ? e : 0.2f * e;
                red[tid] = e * W_attn[2 * HH + tid];
            }
            __syncthreads();
            for (int off = 128; off; off >>= 1) {
                if (tid < off) red[tid] += red[tid + off];
                __syncthreads();
            }
            if (tid == 0) g_ae[t] = red[0];
            __syncthreads();
        }
        return;
    }

    if (blk < SB_TZ) {
        // ---- Eg2[t][h]
        if (tid >= HH) return;
        int t = blk - SB_EG2;
        int h = tid;
        float acc = 0.f;
        for (int k = 0; k < HH; k++)
            acc += edge_emb[t * HH + k] * W_gat[(HH + k) * HH + h];
        g_Eg2[t * HH + h] = acc;
        return;
    }

    if (blk < SB_WCAT) {
        // ---- TZ[s][h] (recompute T inline)
        if (tid >= HH) return;
        int s = blk - SB_TZ;
        int h = tid;
        float acc = 0.f;
        for (int k = 0; k < HH; k++) {
            float tk = W_trip[(2 * HH + s) * HH + k] + b_trip[k];
            acc += tk * W_gat[k * HH + h];
        }
        g_TZ[s * HH + h] = acc;
        return;
    }

    {
        // ---- Wcat: 256 blocks, k = blk - SB_WCAT, j = tid (0..1023)
        int k = blk - SB_WCAT;
        int j = tid;
        float out;
        if (j < HH) {
            out = W_trip[k * HH + j];                     // Wa
        } else if (j < 2 * HH) {
            out = W_trip[(HH + k) * HH + (j - HH)];       // Wb
        } else {
            int jj = j & (HH - 1);
            const float* wrow = (j < 3 * HH) ? &W_trip[k * HH]
                                             : &W_trip[(HH + k) * HH];
            float acc = 0.f;
            for (int m = 0; m < HH; m++)
                acc += wrow[m] * W_gat[m * HH + jj];
            out = acc;                                     // Wa@Wg1 / Wb@Wg1
        }
        g_Wcat[k * GN + j] = out;
    }
}

// ---------------- prefix phase B: add chunk offsets --------------------------
__global__ __launch_bounds__(256) void k_prefix_fix() {
    int b = blockIdx.x / 7;
    int c = blockIdx.x % 7 + 1;          // chunks 1..7
    int h = threadIdx.x;
    float off = 0.f;
    for (int j = 0; j < c; j++)
        off += g_ptot[((b << 3) + j) * HH + h];
    float* cs = g_CS + (size_t)b * CSROWS * HH + h;
    int t0 = c * CHROWS;
    #pragma unroll
    for (int r = 0; r < CHROWS; r++)
        cs[(size_t)(t0 + r + 1) * HH] += off;
}

// ---------------- SGEMM: Y[4384,1024] = CS[4384,256] @ Wcat[256,1024] --------
__global__ __launch_bounds__(256) void k_gemm2() {
    __shared__ float As[8][128];
    __shared__ float Bs[8][128];
    int tid = threadIdx.x;
    int tx = tid & 15;
    int ty = tid >> 4;
    int m_base = blockIdx.y * 128;
    int n_base = blockIdx.x * 128;

    int a_row = tid >> 1;
    int a_col = (tid & 1) * 4;
    int b_row = tid >> 5;
    int b_col = (tid & 31) * 4;

    bool a_ok = (m_base + a_row) < GM;
    const float* a_src = &g_CS[(size_t)(m_base + a_row) * HH + a_col];
    const float* b_src = &g_Wcat[(size_t)b_row * GN + n_base + b_col];

    float acc[8][8];
    #pragma unroll
    for (int i = 0; i < 8; i++)
        #pragma unroll
        for (int j = 0; j < 8; j++) acc[i][j] = 0.f;

    for (int k0 = 0; k0 < HH; k0 += 8) {
        float4 av = make_float4(0.f, 0.f, 0.f, 0.f);
        if (a_ok) av = *reinterpret_cast<const float4*>(a_src + k0);
        float4 bv = *reinterpret_cast<const float4*>(b_src + (size_t)k0 * GN);
        As[a_col + 0][a_row] = av.x;
        As[a_col + 1][a_row] = av.y;
        As[a_col + 2][a_row] = av.z;
        As[a_col + 3][a_row] = av.w;
        *reinterpret_cast<float4*>(&Bs[b_row][b_col]) = bv;
        __syncthreads();
        #pragma unroll
        for (int k = 0; k < 8; k++) {
            float4 a0 = *reinterpret_cast<const float4*>(&As[k][ty * 4]);
            float4 a1 = *reinterpret_cast<const float4*>(&As[k][ty * 4 + 64]);
            float4 b0 = *reinterpret_cast<const float4*>(&Bs[k][tx * 4]);
            float4 b1 = *reinterpret_cast<const float4*>(&Bs[k][tx * 4 + 64]);
            float ar[8] = {a0.x, a0.y, a0.z, a0.w, a1.x, a1.y, a1.z, a1.w};
            float br[8] = {b0.x, b0.y, b0.z, b0.w, b1.x, b1.y, b1.z, b1.w};
            #pragma unroll
            for (int i = 0; i < 8; i++)
                #pragma unroll
                for (int j = 0; j < 8; j++)
                    acc[i][j] += ar[i] * br[j];
        }
        __syncthreads();
    }

    #pragma unroll
    for (int g = 0; g < 2; g++) {
        #pragma unroll
        for (int i = 0; i < 4; i++) {
            int m = m_base + g * 64 + ty * 4 + i;
            if (m < GM) {
                float* dst = &g_Y[(size_t)m * GN + n_base];
                *reinterpret_cast<float4*>(dst + tx * 4) =
                    make_float4(acc[g * 4 + i][0], acc[g * 4 + i][1],
                                acc[g * 4 + i][2], acc[g * 4 + i][3]);
                *reinterpret_cast<float4*>(dst + tx * 4 + 64) =
                    make_float4(acc[g * 4 + i][4], acc[g * 4 + i][5],
                                acc[g * 4 + i][6], acc[g * 4 + i][7]);
            }
        }
    }
}

// ---------------- node / Z / a_src materialization ---------------------------
__global__ __launch_bounds__(256) void k_node(const int* __restrict__ asp_st,
                                              const int* __restrict__ asp_len,
                                              const int* __restrict__ opi_st,
                                              const int* __restrict__ opi_len,
                                              const int* __restrict__ sent,
                                              const float* __restrict__ W_attn) {
    __shared__ float red8[8];
    int bn = blockIdx.x;
    int b = bn >> 9;
    int h = threadIdx.x;
    int as = asp_st[bn], al = asp_len[bn];
    int os = opi_st[bn], ol = opi_len[bn];
    int s = sent[bn];
    float inva = 1.f / (float)(al + 1);
    float invo = 1.f / (float)(ol + 1);
    const float* Yb = g_Y + (size_t)b * CSROWS * GN;
    const float* rA0 = Yb + (size_t)as * GN;
    const float* rA1 = Yb + (size_t)(as + al + 1) * GN;
    const float* rO0 = Yb + (size_t)os * GN;
    const float* rO1 = Yb + (size_t)(os + ol + 1) * GN;

    float nv = (rA1[h] - rA0[h]) * inva + (rO1[HH + h] - rO0[HH + h]) * invo
             + g_T[s * HH + h];
    float zv = (rA1[2 * HH + h] - rA0[2 * HH + h]) * inva
             + (rO1[3 * HH + h] - rO0[3 * HH + h]) * invo
             + g_TZ[s * HH + h];
    g_node[(size_t)bn * HH + h] = nv;
    g_Z[(size_t)bn * HH + h] = zv;

    float ln = (nv >= 0.f) ? nv : 0.2f * nv;
    float v = ln * W_attn[HH + h];
    #pragma unroll
    for (int off = 16; off; off >>= 1)
        v += __shfl_xor_sync(0xffffffffu, v, off);
    if ((h & 31) == 0) red8[h >> 5] = v;
    __syncthreads();
    if (h == 0) {
        float t = 0.f;
        #pragma unroll
        for (int w = 0; w < 8; w++) t += red8[w];
        g_a2[bn] = t;
    }
}

// ---- edges + online softmax + GAT + fused scatter (one warp per target) -----
__global__ __launch_bounds__(256) void k_edges(const int* __restrict__ asp_st,
                                               const int* __restrict__ asp_len,
                                               const int* __restrict__ opi_st,
                                               const int* __restrict__ opi_len,
                                               const float* __restrict__ b_gat) {
    int wg = (blockIdx.x * blockDim.x + threadIdx.x) >> 5;
    if (wg >= BN_TOT) return;
    int lane = threadIdx.x & 31;
    int b = wg >> 9;
    int tgt = wg & 511;
    int bn = wg;

    float nt[8];
    #pragma unroll
    for (int i = 0; i < 8; i++)
        nt[i] = g_node[(size_t)bn * HH + lane + i * 32];

    int key0 = asp_st[bn] * 8 + asp_len[bn];
    int key1 = opi_st[bn] * 8 + opi_len[bn];
    int c = (asp_st[bn] + opi_st[bn]) >> 1;          // center, < 128
    float* addp = &g_add[(((b << 7) + c) << 8)];     // *HH

    float m = -3.0e38f;
    float S = 0.f, e0 = 0.f, e1 = 0.f;
    float acc[8] = {};

    #pragma unroll
    for (int ty = 0; ty < 2; ty++) {
        int key = ty ? key1 : key0;
        const int* st = g_start + (ty * BB + b) * 1025;
        const int* ord = g_order + (ty * BB + b) * NN;
        int s0 = st[key], s1 = st[key + 1];
        float ae = g_ae[ty];
        for (int idx = s0; idx < s1; idx++) {
            int src = ord[idx];
            if (src == tgt) continue;
            int sb = b * NN + src;
            float d = 0.f;
            #pragma unroll
            for (int i = 0; i < 8; i++)
                d += nt[i] * g_node[(size_t)sb * HH + lane + i * 32];
            #pragma unroll
            for (int off = 16; off; off >>= 1)
                d += __shfl_xor_sync(0xffffffffu, d, off);
            if (d > 0.f) {
                float sc = g_a2[sb] + ae;
                float p;
                if (sc > m) {
                    float scale = expf(m - sc);   // 0 on first edge
                    S *= scale; e0 *= scale; e1 *= scale;
                    #pragma unroll
                    for (int i = 0; i < 8; i++) acc[i] *= scale;
                    m = sc;
                    p = 1.f;
                } else {
                    p = expf(sc - m);
                }
                S += p;
                if (ty == 0) e0 += p; else e1 += p;
                #pragma unroll
                for (int i = 0; i < 8; i++)
                    acc[i] += p * g_Z[(size_t)sb * HH + lane + i * 32];
            }
        }
    }

    if (S == 0.f) {  // no neighbors: node passes through (gated later by bflag)
        #pragma unroll
        for (int i = 0; i < 8; i++)
            atomicAdd(&addp[lane + i * 32], nt[i]);
        return;
    }
    if (lane == 0) g_bflag[b] = 1;

    float invS = 1.f / S;
    #pragma unroll
    for (int i = 0; i < 8; i++) {
        int h = lane + i * 32;
        float u = acc[i] * invS + e0 * invS * g_Eg2[h]
                + e1 * invS * g_Eg2[HH + h] + b_gat[h];
        atomicAdd(&addp[h], fmaxf(u, 0.f));
    }
}

// ---------------- fused output: out = emb (+ add on rows < 128) --------------
__global__ __launch_bounds__(256) void k_out(const float* __restrict__ emb,
                                             float* __restrict__ out) {
    int idx = blockIdx.x * blockDim.x + threadIdx.x;   // 8,388,608 float4s
    size_t base = (size_t)idx * 4;
    int b = (int)(base >> 20);                // / (LL*HH)
    int rem = (int)(base & (LL * HH - 1));
    int l = rem >> 8;
    float4 v = *reinterpret_cast<const float4*>(emb + base);
    if (l < CMAX && g_bflag[b]) {
        const float* a = &g_add[((b << 7) + l) * HH + (rem & 255)];
        v.x += a[0]; v.y += a[1]; v.z += a[2]; v.w += a[3];
    }
    *reinterpret_cast<float4*>(out + base) = v;
}

// ---------------- launch -----------------------------------------------------
extern "C" void kernel_launch(void* const* d_in, const int* in_sizes, int n_in,
                              void* d_out, int out_size) {
    const float* emb      = (const float*)d_in[0];
    const float* W_trip   = (const float*)d_in[1];
    const float* b_trip   = (const float*)d_in[2];
    const float* edge_emb = (const float*)d_in[3];
    const float* W_attn   = (const float*)d_in[4];
    // d_in[5] = b_attn (cancels in softmax)
    const float* W_gat    = (const float*)d_in[6];
    const float* b_gat    = (const float*)d_in[7];
    const int* asp_st  = (const int*)d_in[8];
    const int* asp_len = (const int*)d_in[9];
    const int* opi_st  = (const int*)d_in[10];
    const int* opi_len = (const int*)d_in[11];
    const int* sent    = (const int*)d_in[12];
    float* out = (float*)d_out;

    k_setup<<<SB_TOTAL, 1024>>>(emb, W_trip, b_trip, edge_emb, W_attn, W_gat,
                                asp_st, asp_len, opi_st, opi_len);
    k_prefix_fix<<<224, 256>>>();
    {
        dim3 grid(GN / 128, (GM + 127) / 128);
        k_gemm2<<<grid, 256>>>();
    }
    k_node<<<BN_TOT, 256>>>(asp_st, asp_len, opi_st, opi_len, sent, W_attn);
    k_edges<<<(BN_TOT * 32 + 255) / 256, 256>>>(asp_st, asp_len, opi_st, opi_len, b_gat);
    k_out<<<32768, 256>>>(emb, out);
}

// round 9
// speedup vs baseline: 1.6987x; 1.1284x over previous
#include <cuda_runtime.h>
#include <cuda_bf16.h>
#include <math.h>

// Problem constants
#define BB   32
#define LL   4096
#define HH   256
#define NN   512
#define CSROWS 137              // prefix rows 0..136
#define GM   (BB * CSROWS)      // 4384 GEMM rows
#define GN   1024               // [Ya | Yb | Ua | Ub]
#define BN_TOT (BB * NN)        // 16384 nodes
#define CMAX 128                // centers always < 128
#define NCHUNK 8
#define CHROWS 17

// Copy partition: rows [128,4096) of out = emb verbatim.
// Total float4s: 32 * 3968 * 64 = 8,126,464. Per-batch: 253,952 f4.
// Each copy block moves 2048 f4 (256 thr * 8).
#define CP_PER_BLOCK 2048
#define CP_GEMM_BLKS 2048       // f4 [0, 4194304)
#define CP_NODE_BLKS 1024       // f4 [4194304, 6291456)
#define CP_EDGE_BLKS 896        // f4 [6291456, 8126464)
#define CP_NODE_BASE 4194304L
#define CP_EDGE_BASE 6291456L

// GEMM tiles: 8 n-tiles * 35 m-tiles = 280 blocks
#define GEMM_BLKS 280
// k_node: 4 nodes per block
#define NODE_BLKS 4096
// k_edges: 8 warps per block
#define EDGE_BLKS 2048

// ---------------- scratch ----------------------------------------------------
__device__ float g_CS[BB * CSROWS * HH];
__device__ float g_ptot[BB * NCHUNK * HH];
__device__ float g_Wcat[HH * GN];
__device__ float g_Y[GM * GN];
__device__ float g_node[BN_TOT * HH];
__device__ float g_Z[BN_TOT * HH];
__device__ float g_a2[BN_TOT];
__device__ float g_T[3 * HH];
__device__ float g_TZ[3 * HH];
__device__ float g_Eg2[2 * HH];
__device__ float g_ae[2];
__device__ float g_add[BB * CMAX * HH];
__device__ int   g_order[2 * BB * NN];
__device__ int   g_start[2 * BB * 1025];
__device__ int   g_bflag[BB];

// ---------------- inline copy chunk (rows >= 128) ----------------------------
__device__ __forceinline__ void copy_chunk(const float* __restrict__ emb,
                                           float* __restrict__ out,
                                           int cb, long base) {
    const float4* src = reinterpret_cast<const float4*>(emb);
    float4* dst = reinterpret_cast<float4*>(out);
    int t = threadIdx.x;
    long g0 = base + (long)cb * CP_PER_BLOCK;
    #pragma unroll
    for (int i = 0; i < 8; i++) {
        long g = g0 + i * 256 + t;
        int b = (int)(g / 253952L);
        int r = (int)(g - (long)b * 253952L);
        long idx4 = (long)b * 262144L + 8192L + r;
        dst[idx4] = src[idx4];
    }
}

// ---------------- fused setup (identical to R7) ------------------------------
#define SB_BUCKET 256
#define SB_PREFIX 320
#define SB_TAE    576
#define SB_EG2    577
#define SB_TZ    579
#define SB_WCAT   582
#define SB_TOTAL  838

__global__ __launch_bounds__(1024) void k_setup(
    const float* __restrict__ emb,
    const float* __restrict__ W_trip,
    const float* __restrict__ b_trip,
    const float* __restrict__ edge_emb,
    const float* __restrict__ W_attn,
    const float* __restrict__ W_gat,
    const int* __restrict__ asp_st,
    const int* __restrict__ asp_len,
    const int* __restrict__ opi_st,
    const int* __restrict__ opi_len)
{
    int blk = blockIdx.x;
    int tid = threadIdx.x;

    if (blk < SB_BUCKET) {
        int idx = blk * 1024 + tid;
        *reinterpret_cast<float4*>(&g_add[(size_t)idx * 4]) =
            make_float4(0.f, 0.f, 0.f, 0.f);
        if (blk == 0 && tid < BB) g_bflag[tid] = 0;
        return;
    }

    if (blk < SB_PREFIX) {
        __shared__ int cnt[1024];
        __shared__ int offs[1024];
        __shared__ int keys[NN];
        int bx = blk - SB_BUCKET;
        int type = bx >> 5;
        int b = bx & 31;
        int t = tid;

        cnt[t] = 0;
        __syncthreads();
        if (t < NN) {
            int bn = b * NN + t;
            int key = (type == 0) ? asp_st[bn] * 8 + asp_len[bn]
                                  : opi_st[bn] * 8 + opi_len[bn];
            keys[t] = key;
            atomicAdd(&cnt[key], 1);
        }
        __syncthreads();
        int myc = cnt[t];
        for (int off = 1; off < 1024; off <<= 1) {
            int add = (t >= off) ? cnt[t - off] : 0;
            __syncthreads();
            cnt[t] += add;
            __syncthreads();
        }
        int excl = cnt[t] - myc;
        int* st = g_start + (type * BB + b) * 1025;
        st[t] = excl;
        if (t == 1023) st[1024] = cnt[1023];
        offs[t] = excl;
        __syncthreads();
        if (t < NN) {
            int pos = atomicAdd(&offs[keys[t]], 1);
            g_order[(type * BB + b) * NN + pos] = t;
        }
        return;
    }

    if (blk < SB_TAE) {
        if (tid >= HH) return;
        int bx = blk - SB_PREFIX;
        int b = bx >> 3;
        int c = bx & 7;
        int h = tid;
        const float* e = emb + (size_t)b * LL * HH + h;
        float* cs = g_CS + (size_t)b * CSROWS * HH + h;
        if (c == 0) cs[0] = 0.f;
        float acc = 0.f;
        int t0 = c * CHROWS;
        #pragma unroll
        for (int r = 0; r < CHROWS; r++) {
            acc += e[(size_t)(t0 + r) * HH];
            cs[(size_t)(t0 + r + 1) * HH] = acc;
        }
        g_ptot[((b << 3) + c) * HH + h] = acc;
        return;
    }

    if (blk == SB_TAE) {
        __shared__ float red[HH];
        if (tid < HH) {
            #pragma unroll
            for (int s = 0; s < 3; s++)
                g_T[s * HH + tid] = W_trip[(2 * HH + s) * HH + tid] + b_trip[tid];
        }
        for (int t = 0; t < 2; t++) {
            if (tid < HH) {
                float e = edge_emb[t * HH + tid];
                e = (e >= 0.f) ? e : 0.2f * e;
                red[tid] = e * W_attn[2 * HH + tid];
            }
            __syncthreads();
            for (int off = 128; off; off >>= 1) {
                if (tid < off) red[tid] += red[tid + off];
                __syncthreads();
            }
            if (tid == 0) g_ae[t] = red[0];
            __syncthreads();
        }
        return;
    }

    if (blk < SB_TZ) {
        if (tid >= HH) return;
        int t = blk - SB_EG2;
        int h = tid;
        float acc = 0.f;
        for (int k = 0; k < HH; k++)
            acc += edge_emb[t * HH + k] * W_gat[(HH + k) * HH + h];
        g_Eg2[t * HH + h] = acc;
        return;
    }

    if (blk < SB_WCAT) {
        if (tid >= HH) return;
        int s = blk - SB_TZ;
        int h = tid;
        float acc = 0.f;
        for (int k = 0; k < HH; k++) {
            float tk = W_trip[(2 * HH + s) * HH + k] + b_trip[k];
            acc += tk * W_gat[k * HH + h];
        }
        g_TZ[s * HH + h] = acc;
        return;
    }

    {
        int k = blk - SB_WCAT;
        int j = tid;
        float out;
        if (j < HH) {
            out = W_trip[k * HH + j];
        } else if (j < 2 * HH) {
            out = W_trip[(HH + k) * HH + (j - HH)];
        } else {
            int jj = j & (HH - 1);
            const float* wrow = (j < 3 * HH) ? &W_trip[k * HH]
                                             : &W_trip[(HH + k) * HH];
            float acc = 0.f;
            for (int m = 0; m < HH; m++)
                acc += wrow[m] * W_gat[m * HH + jj];
            out = acc;
        }
        g_Wcat[k * GN + j] = out;
    }
}

// ---------------- prefix phase B ---------------------------------------------
__global__ __launch_bounds__(256) void k_prefix_fix() {
    int b = blockIdx.x / 7;
    int c = blockIdx.x % 7 + 1;
    int h = threadIdx.x;
    float off = 0.f;
    for (int j = 0; j < c; j++)
        off += g_ptot[((b << 3) + j) * HH + h];
    float* cs = g_CS + (size_t)b * CSROWS * HH + h;
    int t0 = c * CHROWS;
    #pragma unroll
    for (int r = 0; r < CHROWS; r++)
        cs[(size_t)(t0 + r + 1) * HH] += off;
}

// ---------------- SGEMM + copy tail ------------------------------------------
__global__ __launch_bounds__(256) void k_gemm2(const float* __restrict__ emb,
                                               float* __restrict__ outp) {
    int bx = blockIdx.x;
    if (bx >= GEMM_BLKS) {
        copy_chunk(emb, outp, bx - GEMM_BLKS, 0L);
        return;
    }
    __shared__ float As[8][128];
    __shared__ float Bs[8][128];
    int tid = threadIdx.x;
    int tx = tid & 15;
    int ty = tid >> 4;
    int m_base = (bx >> 3) * 128;
    int n_base = (bx & 7) * 128;

    int a_row = tid >> 1;
    int a_col = (tid & 1) * 4;
    int b_row = tid >> 5;
    int b_col = (tid & 31) * 4;

    bool a_ok = (m_base + a_row) < GM;
    const float* a_src = &g_CS[(size_t)(m_base + a_row) * HH + a_col];
    const float* b_src = &g_Wcat[(size_t)b_row * GN + n_base + b_col];

    float acc[8][8];
    #pragma unroll
    for (int i = 0; i < 8; i++)
        #pragma unroll
        for (int j = 0; j < 8; j++) acc[i][j] = 0.f;

    for (int k0 = 0; k0 < HH; k0 += 8) {
        float4 av = make_float4(0.f, 0.f, 0.f, 0.f);
        if (a_ok) av = *reinterpret_cast<const float4*>(a_src + k0);
        float4 bv = *reinterpret_cast<const float4*>(b_src + (size_t)k0 * GN);
        As[a_col + 0][a_row] = av.x;
        As[a_col + 1][a_row] = av.y;
        As[a_col + 2][a_row] = av.z;
        As[a_col + 3][a_row] = av.w;
        *reinterpret_cast<float4*>(&Bs[b_row][b_col]) = bv;
        __syncthreads();
        #pragma unroll
        for (int k = 0; k < 8; k++) {
            float4 a0 = *reinterpret_cast<const float4*>(&As[k][ty * 4]);
            float4 a1 = *reinterpret_cast<const float4*>(&As[k][ty * 4 + 64]);
            float4 b0 = *reinterpret_cast<const float4*>(&Bs[k][tx * 4]);
            float4 b1 = *reinterpret_cast<const float4*>(&Bs[k][tx * 4 + 64]);
            float ar[8] = {a0.x, a0.y, a0.z, a0.w, a1.x, a1.y, a1.z, a1.w};
            float br[8] = {b0.x, b0.y, b0.z, b0.w, b1.x, b1.y, b1.z, b1.w};
            #pragma unroll
            for (int i = 0; i < 8; i++)
                #pragma unroll
                for (int j = 0; j < 8; j++)
                    acc[i][j] += ar[i] * br[j];
        }
        __syncthreads();
    }

    #pragma unroll
    for (int g = 0; g < 2; g++) {
        #pragma unroll
        for (int i = 0; i < 4; i++) {
            int m = m_base + g * 64 + ty * 4 + i;
            if (m < GM) {
                float* dst = &g_Y[(size_t)m * GN + n_base];
                *reinterpret_cast<float4*>(dst + tx * 4) =
                    make_float4(acc[g * 4 + i][0], acc[g * 4 + i][1],
                                acc[g * 4 + i][2], acc[g * 4 + i][3]);
                *reinterpret_cast<float4*>(dst + tx * 4 + 64) =
                    make_float4(acc[g * 4 + i][4], acc[g * 4 + i][5],
                                acc[g * 4 + i][6], acc[g * 4 + i][7]);
            }
        }
    }
}

// ---------------- node / Z / a2 (vectorized, 4 nodes/block) + copy tail ------
__global__ __launch_bounds__(256) void k_node(const int* __restrict__ asp_st,
                                              const int* __restrict__ asp_len,
                                              const int* __restrict__ opi_st,
                                              const int* __restrict__ opi_len,
                                              const int* __restrict__ sent,
                                              const float* __restrict__ W_attn,
                                              const float* __restrict__ emb,
                                              float* __restrict__ outp) {
    int bx = blockIdx.x;
    if (bx >= NODE_BLKS) {
        copy_chunk(emb, outp, bx - NODE_BLKS, CP_NODE_BASE);
        return;
    }
    __shared__ float red[4][2];
    int tid = threadIdx.x;
    int nl = tid >> 6;              // node within block: 0..3
    int g = tid & 63;               // float4 lane: h = 4g
    int bn = (bx << 2) + nl;
    int b = bn >> 9;
    int as = asp_st[bn], al = asp_len[bn];
    int os = opi_st[bn], ol = opi_len[bn];
    int s = sent[bn];
    float inva = 1.f / (float)(al + 1);
    float invo = 1.f / (float)(ol + 1);
    const float* Yb = g_Y + (size_t)b * CSROWS * GN;
    const float* rA0 = Yb + (size_t)as * GN;
    const float* rA1 = Yb + (size_t)(as + al + 1) * GN;
    const float* rO0 = Yb + (size_t)os * GN;
    const float* rO1 = Yb + (size_t)(os + ol + 1) * GN;
    int h4 = g * 4;

    float4 a0 = *reinterpret_cast<const float4*>(rA0 + h4);
    float4 a1 = *reinterpret_cast<const float4*>(rA1 + h4);
    float4 o0 = *reinterpret_cast<const float4*>(rO0 + HH + h4);
    float4 o1 = *reinterpret_cast<const float4*>(rO1 + HH + h4);
    float4 t4 = *reinterpret_cast<const float4*>(g_T + s * HH + h4);
    float4 nv;
    nv.x = (a1.x - a0.x) * inva + (o1.x - o0.x) * invo + t4.x;
    nv.y = (a1.y - a0.y) * inva + (o1.y - o0.y) * invo + t4.y;
    nv.z = (a1.z - a0.z) * inva + (o1.z - o0.z) * invo + t4.z;
    nv.w = (a1.w - a0.w) * inva + (o1.w - o0.w) * invo + t4.w;

    float4 za0 = *reinterpret_cast<const float4*>(rA0 + 2 * HH + h4);
    float4 za1 = *reinterpret_cast<const float4*>(rA1 + 2 * HH + h4);
    float4 zo0 = *reinterpret_cast<const float4*>(rO0 + 3 * HH + h4);
    float4 zo1 = *reinterpret_cast<const float4*>(rO1 + 3 * HH + h4);
    float4 tz4 = *reinterpret_cast<const float4*>(g_TZ + s * HH + h4);
    float4 zv;
    zv.x = (za1.x - za0.x) * inva + (zo1.x - zo0.x) * invo + tz4.x;
    zv.y = (za1.y - za0.y) * inva + (zo1.y - zo0.y) * invo + tz4.y;
    zv.z = (za1.z - za0.z) * inva + (zo1.z - zo0.z) * invo + tz4.z;
    zv.w = (za1.w - za0.w) * inva + (zo1.w - zo0.w) * invo + tz4.w;

    *reinterpret_cast<float4*>(g_node + (size_t)bn * HH + h4) = nv;
    *reinterpret_cast<float4*>(g_Z + (size_t)bn * HH + h4) = zv;

    float4 w4 = *reinterpret_cast<const float4*>(W_attn + HH + h4);
    float lx = (nv.x >= 0.f) ? nv.x : 0.2f * nv.x;
    float ly = (nv.y >= 0.f) ? nv.y : 0.2f * nv.y;
    float lz = (nv.z >= 0.f) ? nv.z : 0.2f * nv.z;
    float lw = (nv.w >= 0.f) ? nv.w : 0.2f * nv.w;
    float v = lx * w4.x + ly * w4.y + lz * w4.z + lw * w4.w;
    #pragma unroll
    for (int off = 16; off; off >>= 1)
        v += __shfl_xor_sync(0xffffffffu, v, off);
    if ((g & 31) == 0) red[nl][g >> 5] = v;
    __syncthreads();
    if (g == 0) g_a2[bn] = red[nl][0] + red[nl][1];
}

// ---- edges + online softmax + GAT + fused scatter + copy tail ---------------
__global__ __launch_bounds__(256) void k_edges(const int* __restrict__ asp_st,
                                               const int* __restrict__ asp_len,
                                               const int* __restrict__ opi_st,
                                               const int* __restrict__ opi_len,
                                               const float* __restrict__ b_gat,
                                               const float* __restrict__ emb,
                                               float* __restrict__ outp) {
    int bx = blockIdx.x;
    if (bx >= EDGE_BLKS) {
        copy_chunk(emb, outp, bx - EDGE_BLKS, CP_EDGE_BASE);
        return;
    }
    int tid = threadIdx.x;
    int wg = bx * 8 + (tid >> 5);
    int lane = tid & 31;
    int b = wg >> 9;
    int tgt = wg & 511;
    int bn = wg;

    float nt[8];
    #pragma unroll
    for (int i = 0; i < 8; i++)
        nt[i] = g_node[(size_t)bn * HH + lane + i * 32];

    int key0 = asp_st[bn] * 8 + asp_len[bn];
    int key1 = opi_st[bn] * 8 + opi_len[bn];
    int c = (asp_st[bn] + opi_st[bn]) >> 1;
    float* addp = &g_add[(((b << 7) + c) << 8)];

    float m = -3.0e38f;
    float S = 0.f, e0 = 0.f, e1 = 0.f;
    float acc[8] = {};

    #pragma unroll
    for (int ty = 0; ty < 2; ty++) {
        int key = ty ? key1 : key0;
        const int* st = g_start + (ty * BB + b) * 1025;
        const int* ord = g_order + (ty * BB + b) * NN;
        int s0 = st[key], s1 = st[key + 1];
        float ae = g_ae[ty];
        for (int idx = s0; idx < s1; idx++) {
            int src = ord[idx];
            if (src == tgt) continue;
            int sb = b * NN + src;
            float d = 0.f;
            #pragma unroll
            for (int i = 0; i < 8; i++)
                d += nt[i] * g_node[(size_t)sb * HH + lane + i * 32];
            #pragma unroll
            for (int off = 16; off; off >>= 1)
                d += __shfl_xor_sync(0xffffffffu, d, off);
            if (d > 0.f) {
                float sc = g_a2[sb] + ae;
                float p;
                if (sc > m) {
                    float scale = expf(m - sc);
                    S *= scale; e0 *= scale; e1 *= scale;
                    #pragma unroll
                    for (int i = 0; i < 8; i++) acc[i] *= scale;
                    m = sc;
                    p = 1.f;
                } else {
                    p = expf(sc - m);
                }
                S += p;
                if (ty == 0) e0 += p; else e1 += p;
                #pragma unroll
                for (int i = 0; i < 8; i++)
                    acc[i] += p * g_Z[(size_t)sb * HH + lane + i * 32];
            }
        }
    }

    if (S == 0.f) {
        #pragma unroll
        for (int i = 0; i < 8; i++)
            atomicAdd(&addp[lane + i * 32], nt[i]);
        return;
    }
    if (lane == 0) g_bflag[b] = 1;

    float invS = 1.f / S;
    #pragma unroll
    for (int i = 0; i < 8; i++) {
        int h = lane + i * 32;
        float u = acc[i] * invS + e0 * invS * g_Eg2[h]
                + e1 * invS * g_Eg2[HH + h] + b_gat[h];
        atomicAdd(&addp[h], fmaxf(u, 0.f));
    }
}

// ---------------- rows [0,128): out = emb + gated add ------------------------
__global__ __launch_bounds__(256) void k_out_low(const float* __restrict__ emb,
                                                 float* __restrict__ out) {
    int idx = blockIdx.x * blockDim.x + threadIdx.x;  // 0..262143 f4
    int b = idx >> 13;
    int r = idx & 8191;
    size_t src4 = (size_t)b * 262144 + r;
    float4 v = reinterpret_cast<const float4*>(emb)[src4];
    if (g_bflag[b]) {
        const float4 a = reinterpret_cast<const float4*>(g_add)[idx];
        v.x += a.x; v.y += a.y; v.z += a.z; v.w += a.w;
    }
    reinterpret_cast<float4*>(out)[src4] = v;
}

// ---------------- launch -----------------------------------------------------
extern "C" void kernel_launch(void* const* d_in, const int* in_sizes, int n_in,
                              void* d_out, int out_size) {
    const float* emb      = (const float*)d_in[0];
    const float* W_trip   = (const float*)d_in[1];
    const float* b_trip   = (const float*)d_in[2];
    const float* edge_emb = (const float*)d_in[3];
    const float* W_attn   = (const float*)d_in[4];
    const float* W_gat    = (const float*)d_in[6];
    const float* b_gat    = (const float*)d_in[7];
    const int* asp_st  = (const int*)d_in[8];
    const int* asp_len = (const int*)d_in[9];
    const int* opi_st  = (const int*)d_in[10];
    const int* opi_len = (const int*)d_in[11];
    const int* sent    = (const int*)d_in[12];
    float* out = (float*)d_out;

    k_setup<<<SB_TOTAL, 1024>>>(emb, W_trip, b_trip, edge_emb, W_attn, W_gat,
                                asp_st, asp_len, opi_st, opi_len);
    k_prefix_fix<<<224, 256>>>();
    k_gemm2<<<GEMM_BLKS + CP_GEMM_BLKS, 256>>>(emb, out);
    k_node<<<NODE_BLKS + CP_NODE_BLKS, 256>>>(asp_st, asp_len, opi_st, opi_len,
                                              sent, W_attn, emb, out);
    k_edges<<<EDGE_BLKS + CP_EDGE_BLKS, 256>>>(asp_st, asp_len, opi_st, opi_len,
                                               b_gat, emb, out);
    k_out_low<<<1024, 256>>>(emb, out);
}